// round 14
// baseline (speedup 1.0000x reference)
#include <cuda_runtime.h>
#include <cuda_bf16.h>
#include <cuda_fp16.h>

#define N0 8192
#define N1 4096
#define N2 2048
#define STEPS 100
#define INF1 0.28f
#define INF2 0.20f
#define WSCALE 4096.0f
#define INV_WSCALE (1.0f / 4096.0f)

// ---------------- scratch (device globals; no allocation in kernel_launch) ----
__device__ __align__(16) unsigned char g_W0f8[(size_t)N0 * N1];  // 32 MB row-major
__device__ __align__(16) unsigned char g_W1f8[(size_t)N1 * N2];  // 8 MB row-major
__device__ __align__(16) unsigned char g_W0T[(size_t)N1 * N0];   // 32 MB: W0T[j][k]=W0[k][j]
__device__ __align__(16) unsigned char g_W1T[(size_t)N2 * N1];   // 8 MB:  W1T[s][j]=W1[j][s]
__device__ float g_e0[N0];
__device__ float g_e1[N1];
__device__ float g_ract1[N1], g_rout1[N1];
__device__ float g_ract2[N2], g_rout2[N2];
__device__ __align__(16) __half g_rh1[N1];   // f16 copy of r_out1 (for k_errs dots)
__device__ __align__(16) __half g_rh2[N2];   // f16 copy of r_out2

__device__ __forceinline__ float sigm3(float x) {
    return 1.0f / (1.0f + expf(3.0f - x));   // sigmoid(x - 3)
}

// pack 4 floats -> 4 e4m3 bytes (byte0 = v.x ... byte3 = v.w)
__device__ __forceinline__ unsigned pack4_e4m3(float4 v) {
    unsigned short lo, hi;
    asm("cvt.rn.satfinite.e4m3x2.f32 %0, %1, %2;" : "=h"(lo) : "f"(v.y), "f"(v.x));
    asm("cvt.rn.satfinite.e4m3x2.f32 %0, %1, %2;" : "=h"(hi) : "f"(v.w), "f"(v.z));
    return (unsigned)lo | ((unsigned)hi << 16);
}

// decode u32 (4 e4m3 bytes) -> two __half2 (a = bytes 0,1 ; b = bytes 2,3)
__device__ __forceinline__ void u32_to_2h2(unsigned u, __half2& a, __half2& b) {
    unsigned ra, rb;
    asm("{\n\t"
        ".reg .b16 lo, hi;\n\t"
        "mov.b32 {lo, hi}, %2;\n\t"
        "cvt.rn.f16x2.e4m3x2 %0, lo;\n\t"
        "cvt.rn.f16x2.e4m3x2 %1, hi;\n\t"
        "}"
        : "=r"(ra), "=r"(rb) : "r"(u));
    a = *reinterpret_cast<__half2*>(&ra);
    b = *reinterpret_cast<__half2*>(&rb);
}

__device__ __forceinline__ __half2 as_h2(unsigned u) {
    return *reinterpret_cast<__half2*>(&u);
}

// dot of one fp8 uint4 (16 w) against 16 r halves, f16 chain -> f32 acc (proven path)
__device__ __forceinline__ void dot16_f8(uint4 wq, uint4 rq0, uint4 rq1, float& acc) {
    __half2 h = __float2half2_rn(0.0f);
    __half2 a, b;
    u32_to_2h2(wq.x, a, b);
    h = __hfma2(a, as_h2(rq0.x), h);
    h = __hfma2(b, as_h2(rq0.y), h);
    u32_to_2h2(wq.y, a, b);
    h = __hfma2(a, as_h2(rq0.z), h);
    h = __hfma2(b, as_h2(rq0.w), h);
    u32_to_2h2(wq.z, a, b);
    h = __hfma2(a, as_h2(rq1.x), h);
    h = __hfma2(b, as_h2(rq1.y), h);
    u32_to_2h2(wq.w, a, b);
    h = __hfma2(a, as_h2(rq1.z), h);
    h = __hfma2(b, as_h2(rq1.w), h);
    float2 f = __half22float2(h);
    acc += f.x + f.y;
}

// fma of one fp8 uint4 (16 w) against 16 f32 e values, full f32
__device__ __forceinline__ void fma16_f8_f32(uint4 wq, const float* ep, float& a0, float& a1) {
    __half2 ha, hb;
    float2 f;
    u32_to_2h2(wq.x, ha, hb);
    f = __half22float2(ha); a0 = fmaf(f.x, ep[0], a0);  a1 = fmaf(f.y, ep[1], a1);
    f = __half22float2(hb); a0 = fmaf(f.x, ep[2], a0);  a1 = fmaf(f.y, ep[3], a1);
    u32_to_2h2(wq.y, ha, hb);
    f = __half22float2(ha); a0 = fmaf(f.x, ep[4], a0);  a1 = fmaf(f.y, ep[5], a1);
    f = __half22float2(hb); a0 = fmaf(f.x, ep[6], a0);  a1 = fmaf(f.y, ep[7], a1);
    u32_to_2h2(wq.z, ha, hb);
    f = __half22float2(ha); a0 = fmaf(f.x, ep[8], a0);  a1 = fmaf(f.y, ep[9], a1);
    f = __half22float2(hb); a0 = fmaf(f.x, ep[10], a0); a1 = fmaf(f.y, ep[11], a1);
    u32_to_2h2(wq.w, ha, hb);
    f = __half22float2(ha); a0 = fmaf(f.x, ep[12], a0); a1 = fmaf(f.y, ep[13], a1);
    f = __half22float2(hb); a0 = fmaf(f.x, ep[14], a0); a1 = fmaf(f.y, ep[15], a1);
}

// ---------------- one-time per-launch setup ----------------------------------
__global__ void k_convert(const float* __restrict__ W0, const float* __restrict__ W1) {
    size_t i = (size_t)blockIdx.x * blockDim.x + threadIdx.x;
    const size_t n0q = (size_t)N0 * N1 / 4;
    const size_t n1q = (size_t)N1 * N2 / 4;
    if (i < n0q) {
        float4 v = __ldg((const float4*)W0 + i);
        v.x *= WSCALE; v.y *= WSCALE; v.z *= WSCALE; v.w *= WSCALE;
        reinterpret_cast<unsigned*>(g_W0f8)[i] = pack4_e4m3(v);
    } else if (i < n0q + n1q) {
        size_t j = i - n0q;
        float4 v = __ldg((const float4*)W1 + j);
        v.x *= WSCALE; v.y *= WSCALE; v.z *= WSCALE; v.w *= WSCALE;
        reinterpret_cast<unsigned*>(g_W1f8)[j] = pack4_e4m3(v);
    }
}

// dead-simple 32x32 byte-tile transpose: dst[c][r] = src[r][c]
__global__ void k_tr8(const unsigned char* __restrict__ src,
                      unsigned char* __restrict__ dst, int R, int C) {
    __shared__ unsigned char t[32][33];
    int r0 = blockIdx.x * 32, c0 = blockIdx.y * 32;
    t[threadIdx.y][threadIdx.x] = src[(size_t)(r0 + threadIdx.y) * C + c0 + threadIdx.x];
    __syncthreads();
    dst[(size_t)(c0 + threadIdx.y) * R + r0 + threadIdx.x] = t[threadIdx.x][threadIdx.y];
}

__global__ void k_init() {
    int j = blockIdx.x * blockDim.x + threadIdx.x;
    float r0 = sigm3(-2.0f);
    if (j < N1) {
        g_ract1[j] = -2.0f;
        g_rout1[j] = r0;
        g_rh1[j] = __float2half(r0);
    } else if (j < N1 + N2) {
        int k = j - N1;
        g_ract2[k] = -2.0f;
        g_rout2[k] = r0;
        g_rh2[k] = __float2half(r0);
    }
}

// ---------------- per-step K1: error matvecs (identical to proven R8 forward) --
// e0 = frame - W0 @ r1 (8192 rows); e1 = r1 - W1 @ r2 (4096 rows). 1 row/warp.
__global__ void __launch_bounds__(256) k_errs(const float* __restrict__ frame) {
    int tid = threadIdx.x, lane = tid & 31, warp = tid >> 5;
    int b = blockIdx.x;
    if (b < 1024) {
        int row = b * 8 + warp;              // 0..8191
        const uint4* w0 = (const uint4*)(g_W0f8 + (size_t)row * N1);
        const uint4* rp = (const uint4*)g_rh1;   // 512 uint4
        float a0 = 0.f;
        #pragma unroll
        for (int i = 0; i < 8; i++) {        // 256 uint4/row
            int c = lane + i * 32;
            uint4 rq0 = __ldg(rp + 2 * c);
            uint4 rq1 = __ldg(rp + 2 * c + 1);
            dot16_f8(__ldg(w0 + c), rq0, rq1, a0);
        }
        #pragma unroll
        for (int o = 16; o; o >>= 1) a0 += __shfl_xor_sync(0xFFFFFFFFu, a0, o);
        if (lane == 0) g_e0[row] = frame[row] - a0 * INV_WSCALE;
    } else {
        int row = (b - 1024) * 8 + warp;     // 0..4095
        const uint4* w0 = (const uint4*)(g_W1f8 + (size_t)row * N2);
        const uint4* rp = (const uint4*)g_rh2;   // 256 uint4
        float a0 = 0.f;
        #pragma unroll
        for (int i = 0; i < 4; i++) {        // 128 uint4/row
            int c = lane + i * 32;
            uint4 rq0 = __ldg(rp + 2 * c);
            uint4 rq1 = __ldg(rp + 2 * c + 1);
            dot16_f8(__ldg(w0 + c), rq0, rq1, a0);
        }
        #pragma unroll
        for (int o = 16; o; o >>= 1) a0 += __shfl_xor_sync(0xFFFFFFFFu, a0, o);
        if (lane == 0) g_e1[row] = g_rout1[row] - a0 * INV_WSCALE;
    }
}

// ---------------- per-step K2: bu matvecs in FULL f32 + fused state update -----
// bu1[j] = W0T[j,:].e0 (f32 e from smem); bu2[s] = W1T[s,:].e1. 1 row/warp.
// Blocks [0,512): layer1. Blocks [512,768): layer2.
__global__ void __launch_bounds__(256) k_bu() {
    __shared__ float se[N0];   // 32 KB; layer2 uses first 16 KB
    int tid = threadIdx.x, lane = tid & 31, warp = tid >> 5;
    int b = blockIdx.x;
    if (b < 512) {
        // stage e0 (f32) into smem
        const float4* e4 = (const float4*)g_e0;
        float4* s4 = (float4*)se;
        #pragma unroll
        for (int i = 0; i < 8; i++) s4[tid + i * 256] = __ldg(e4 + tid + i * 256);
        __syncthreads();
        int row = b * 8 + warp;              // 0..4095
        const uint4* w = (const uint4*)(g_W0T + (size_t)row * N0);
        float a0 = 0.f, a1 = 0.f;
        #pragma unroll 4
        for (int i = 0; i < 16; i++) {       // 512 uint4/row
            int c = lane + i * 32;
            fma16_f8_f32(__ldg(w + c), se + c * 16, a0, a1);
        }
        a0 += a1;
        #pragma unroll
        for (int o = 16; o; o >>= 1) a0 += __shfl_xor_sync(0xFFFFFFFFu, a0, o);
        if (lane == 0) {
            float bu1 = a0 * INV_WSCALE;
            float na = g_ract1[row] + INF1 * (bu1 - g_e1[row]);
            g_ract1[row] = na;
            float ro = sigm3(na);
            g_rout1[row] = ro;
            g_rh1[row] = __float2half(ro);
        }
    } else {
        const float4* e4 = (const float4*)g_e1;
        float4* s4 = (float4*)se;
        #pragma unroll
        for (int i = 0; i < 4; i++) s4[tid + i * 256] = __ldg(e4 + tid + i * 256);
        __syncthreads();
        int row = (b - 512) * 8 + warp;      // 0..2047
        const uint4* w = (const uint4*)(g_W1T + (size_t)row * N1);
        float a0 = 0.f, a1 = 0.f;
        #pragma unroll
        for (int i = 0; i < 8; i++) {        // 256 uint4/row
            int c = lane + i * 32;
            fma16_f8_f32(__ldg(w + c), se + c * 16, a0, a1);
        }
        a0 += a1;
        #pragma unroll
        for (int o = 16; o; o >>= 1) a0 += __shfl_xor_sync(0xFFFFFFFFu, a0, o);
        if (lane == 0) {
            float bu2 = a0 * INV_WSCALE;
            float na = g_ract2[row] + INF2 * bu2;
            g_ract2[row] = na;
            float ro = sigm3(na);
            g_rout2[row] = ro;
            g_rh2[row] = __float2half(ro);
        }
    }
}

// ---------------- output assembly ---------------------------------------------
__global__ void k_output(float* __restrict__ out) {
    int i = blockIdx.x * blockDim.x + threadIdx.x;
    if (i < N0) {
        out[i] = g_e0[i];
    } else if (i < N0 + N1) {
        out[i] = g_e1[i - N0];
    } else if (i < N0 + 2 * N1) {
        out[i] = g_rout1[i - N0 - N1];
    } else if (i < N0 + 2 * N1 + N2) {
        out[i] = g_rout2[i - N0 - 2 * N1];
    }
}

extern "C" void kernel_launch(void* const* d_in, const int* in_sizes, int n_in,
                              void* d_out, int out_size) {
    const float* frame = (const float*)d_in[0];
    const float* W0    = (const float*)d_in[1];
    const float* W1    = (const float*)d_in[2];
    float* out = (float*)d_out;

    const size_t totq = ((size_t)N0 * N1 + (size_t)N1 * N2) / 4;
    int cvt_blocks = (int)((totq + 255) / 256);
    k_convert<<<cvt_blocks, 256>>>(W0, W1);
    {
        dim3 blk(32, 32);
        dim3 g0(N0 / 32, N1 / 32);   // W0 (8192x4096) -> W0T (4096x8192)
        k_tr8<<<g0, blk>>>(g_W0f8, g_W0T, N0, N1);
        dim3 g1(N1 / 32, N2 / 32);   // W1 (4096x2048) -> W1T (2048x4096)
        k_tr8<<<g1, blk>>>(g_W1f8, g_W1T, N1, N2);
    }
    k_init<<<24, 256>>>();

    for (int t = 0; t < STEPS; t++) {
        k_errs<<<1536, 256>>>(frame);
        k_bu<<<768, 256>>>();
    }
    k_output<<<72, 256>>>(out);
}

// round 15
// speedup vs baseline: 2.1939x; 2.1939x over previous
#include <cuda_runtime.h>
#include <cuda_bf16.h>
#include <cuda_fp16.h>

#define N0 8192
#define N1 4096
#define N2 2048
#define STEPS 100
#define INF1 0.28f
#define INF2 0.20f
#define WSCALE 4096.0f
#define INV_WSCALE (1.0f / 4096.0f)

// transpose partial chunks: 16 rows each
#define CH0 512   // 8192 / 16
#define CH1 256   // 4096 / 16

// ---------------- scratch (device globals; no allocation in kernel_launch) ----
__device__ __align__(16) unsigned char g_W0f8[(size_t)N0 * N1];   // 32 MB, e4m3 = W0 * 4096
__device__ __align__(16) unsigned char g_W1f8[(size_t)N1 * N2];   // 8 MB,  e4m3 = W1 * 4096
__device__ float g_e0[N0];
__device__ float g_e1[N1];
__device__ float g_ract1[N1], g_rout1[N1];
__device__ float g_ract2[N2], g_rout2[N2];
__device__ __align__(16) __half g_rh1[N1];          // f16 copy of r_out1
__device__ __align__(16) __half g_rh2[N2];          // f16 copy of r_out2
__device__ float g_pbu1[(size_t)CH0 * N1];          // 8 MB
__device__ float g_pbu2[(size_t)CH1 * N2];          // 2 MB

__device__ __forceinline__ float sigm3(float x) {
    // sigmoid(x - 3)
    return 1.0f / (1.0f + expf(3.0f - x));
}

// pack 4 floats -> 4 e4m3 bytes (byte0 = v.x ... byte3 = v.w)
__device__ __forceinline__ unsigned pack4_e4m3(float4 v) {
    unsigned short lo, hi;
    asm("cvt.rn.satfinite.e4m3x2.f32 %0, %1, %2;" : "=h"(lo) : "f"(v.y), "f"(v.x));
    asm("cvt.rn.satfinite.e4m3x2.f32 %0, %1, %2;" : "=h"(hi) : "f"(v.w), "f"(v.z));
    return (unsigned)lo | ((unsigned)hi << 16);
}

// decode u32 (4 e4m3) -> two __half2 (a = vals 0,1 ; b = vals 2,3)
__device__ __forceinline__ void u32_to_2h2(unsigned u, __half2& a, __half2& b) {
    unsigned ra, rb;
    asm("{\n\t"
        ".reg .b16 lo, hi;\n\t"
        "mov.b32 {lo, hi}, %2;\n\t"
        "cvt.rn.f16x2.e4m3x2 %0, lo;\n\t"
        "cvt.rn.f16x2.e4m3x2 %1, hi;\n\t"
        "}"
        : "=r"(ra), "=r"(rb) : "r"(u));
    a = *reinterpret_cast<__half2*>(&ra);
    b = *reinterpret_cast<__half2*>(&rb);
}

__device__ __forceinline__ __half2 as_h2(unsigned u) {
    return *reinterpret_cast<__half2*>(&u);
}

// ---------------- one-time per-launch setup ----------------------------------
__global__ void k_convert(const float* __restrict__ W0, const float* __restrict__ W1) {
    size_t i = (size_t)blockIdx.x * blockDim.x + threadIdx.x;
    const size_t n0q = (size_t)N0 * N1 / 4;
    const size_t n1q = (size_t)N1 * N2 / 4;
    if (i < n0q) {
        float4 v = __ldg((const float4*)W0 + i);
        v.x *= WSCALE; v.y *= WSCALE; v.z *= WSCALE; v.w *= WSCALE;
        reinterpret_cast<unsigned*>(g_W0f8)[i] = pack4_e4m3(v);
    } else if (i < n0q + n1q) {
        size_t j = i - n0q;
        float4 v = __ldg((const float4*)W1 + j);
        v.x *= WSCALE; v.y *= WSCALE; v.z *= WSCALE; v.w *= WSCALE;
        reinterpret_cast<unsigned*>(g_W1f8)[j] = pack4_e4m3(v);
    }
}

__global__ void k_init() {
    int j = blockIdx.x * blockDim.x + threadIdx.x;
    float r0 = sigm3(-2.0f);
    if (j < N1) {
        g_ract1[j] = -2.0f;
        g_rout1[j] = r0;
        g_rh1[j] = __float2half(r0);
    } else if (j < N1 + N2) {
        int k = j - N1;
        g_ract2[k] = -2.0f;
        g_rout2[k] = r0;
        g_rh2[k] = __float2half(r0);
    }
}

// dot of one fp8 uint4 (16 w) against 16 r halves (2 uint4 of __half2), f16 chain
__device__ __forceinline__ void dot16_f8(uint4 wq, uint4 rq0, uint4 rq1, float& acc) {
    __half2 h = __float2half2_rn(0.0f);
    __half2 a, b;
    u32_to_2h2(wq.x, a, b);
    h = __hfma2(a, as_h2(rq0.x), h);
    h = __hfma2(b, as_h2(rq0.y), h);
    u32_to_2h2(wq.y, a, b);
    h = __hfma2(a, as_h2(rq0.z), h);
    h = __hfma2(b, as_h2(rq0.w), h);
    u32_to_2h2(wq.z, a, b);
    h = __hfma2(a, as_h2(rq1.x), h);
    h = __hfma2(b, as_h2(rq1.y), h);
    u32_to_2h2(wq.w, a, b);
    h = __hfma2(a, as_h2(rq1.z), h);
    h = __hfma2(b, as_h2(rq1.w), h);
    float2 f = __half22float2(h);
    acc += f.x + f.y;
}

// ---------------- per-step K1: forward matvecs --------------------------------
// e0 = frame - W0 @ r1 ;  e1 = r1 - W1 @ r2
// 1 row per warp. Blocks [0,1024): W0 (8192 warps -> 8192 rows).
// Blocks [1024,1536): W1 (4096 warps -> 4096 rows).
__global__ void __launch_bounds__(256) k_forward(const float* __restrict__ frame) {
    int tid = threadIdx.x, lane = tid & 31, warp = tid >> 5;
    int b = blockIdx.x;
    if (b < 1024) {
        int row = b * 8 + warp;              // 0..8191
        const uint4* w0 = (const uint4*)(g_W0f8 + (size_t)row * N1);
        const uint4* rp = (const uint4*)g_rh1;   // 512 uint4 = 4096 halves
        float a0 = 0.f;
        // 256 uint4 per row (16 fp8 each), 8 iters per lane
        #pragma unroll
        for (int i = 0; i < 8; i++) {
            int c = lane + i * 32;
            uint4 rq0 = __ldg(rp + 2 * c);
            uint4 rq1 = __ldg(rp + 2 * c + 1);
            dot16_f8(__ldg(w0 + c), rq0, rq1, a0);
        }
        #pragma unroll
        for (int o = 16; o; o >>= 1) a0 += __shfl_xor_sync(0xFFFFFFFFu, a0, o);
        if (lane == 0) g_e0[row] = frame[row] - a0 * INV_WSCALE;
    } else {
        int row = (b - 1024) * 8 + warp;     // 0..4095
        const uint4* w0 = (const uint4*)(g_W1f8 + (size_t)row * N2);
        const uint4* rp = (const uint4*)g_rh2;   // 256 uint4 = 2048 halves
        float a0 = 0.f;
        // 128 uint4 per row, 4 iters per lane
        #pragma unroll
        for (int i = 0; i < 4; i++) {
            int c = lane + i * 32;
            uint4 rq0 = __ldg(rp + 2 * c);
            uint4 rq1 = __ldg(rp + 2 * c + 1);
            dot16_f8(__ldg(w0 + c), rq0, rq1, a0);
        }
        #pragma unroll
        for (int o = 16; o; o >>= 1) a0 += __shfl_xor_sync(0xFFFFFFFFu, a0, o);
        if (lane == 0) g_e1[row] = g_rout1[row] - a0 * INV_WSCALE;
    }
}

// ---------------- per-step K2: transpose matvec partials -----------------------
// 16-row chunks, thread = 16 consecutive cols (one fp8 uint4 per row, 16 loads
// per thread via a 4-deep register prefetch ring -> MLP=4 guaranteed).
// Blocks [0,1024): W0 (2 colblocks x 512 chunks).
// Blocks [1024,1280): W1 (1 colblock x 256 chunks).
__global__ void __launch_bounds__(128) k_transpose() {
    __shared__ __half2 s_eh[16];
    int tid = threadIdx.x;
    int b = blockIdx.x;

    const unsigned char* wmat;
    float* pbu;
    int col0, row0, chunk, ldw;
    if (b < 1024) {
        int colblock = b & 1;
        chunk = b >> 1;                      // 0..511
        col0 = colblock * 2048 + tid * 16;
        row0 = chunk * 16;
        if (tid < 16) s_eh[tid] = __float2half2_rn(g_e0[row0 + tid]);
        wmat = g_W0f8;
        pbu = g_pbu1;
        ldw = N1;
    } else {
        chunk = b - 1024;                    // 0..255
        col0 = tid * 16;
        row0 = chunk * 16;
        if (tid < 16) s_eh[tid] = __float2half2_rn(g_e1[row0 + tid]);
        wmat = g_W1f8;
        pbu = g_pbu2;
        ldw = N2;
    }
    __syncthreads();

    const unsigned char* wbase = wmat + (size_t)row0 * ldw + col0;

    // 4-deep prefetch ring over 16 row loads
    uint4 p0 = *reinterpret_cast<const uint4*>(wbase + (size_t)0 * ldw);
    uint4 p1 = *reinterpret_cast<const uint4*>(wbase + (size_t)1 * ldw);
    uint4 p2 = *reinterpret_cast<const uint4*>(wbase + (size_t)2 * ldw);
    uint4 p3 = *reinterpret_cast<const uint4*>(wbase + (size_t)3 * ldw);

    __half2 acc[8];
    #pragma unroll
    for (int k = 0; k < 8; k++) acc[k] = __float2half2_rn(0.0f);

    #pragma unroll
    for (int r = 0; r < 16; r++) {
        uint4 u;
        if ((r & 3) == 0) u = p0;
        else if ((r & 3) == 1) u = p1;
        else if ((r & 3) == 2) u = p2;
        else u = p3;
        // refill the just-consumed slot with row r+4
        if (r + 4 < 16) {
            uint4 nv = *reinterpret_cast<const uint4*>(wbase + (size_t)(r + 4) * ldw);
            if ((r & 3) == 0) p0 = nv;
            else if ((r & 3) == 1) p1 = nv;
            else if ((r & 3) == 2) p2 = nv;
            else p3 = nv;
        }
        __half2 ev = s_eh[r];
        __half2 a, bb;
        u32_to_2h2(u.x, a, bb);
        acc[0] = __hfma2(a, ev, acc[0]);
        acc[1] = __hfma2(bb, ev, acc[1]);
        u32_to_2h2(u.y, a, bb);
        acc[2] = __hfma2(a, ev, acc[2]);
        acc[3] = __hfma2(bb, ev, acc[3]);
        u32_to_2h2(u.z, a, bb);
        acc[4] = __hfma2(a, ev, acc[4]);
        acc[5] = __hfma2(bb, ev, acc[5]);
        u32_to_2h2(u.w, a, bb);
        acc[6] = __hfma2(a, ev, acc[6]);
        acc[7] = __hfma2(bb, ev, acc[7]);
    }

    float facc[16];
    #pragma unroll
    for (int k = 0; k < 8; k++) {
        float2 f = __half22float2(acc[k]);
        facc[2 * k]     = f.x;
        facc[2 * k + 1] = f.y;
    }

    float4* outp = reinterpret_cast<float4*>(&pbu[(size_t)chunk * ldw + col0]);
    outp[0] = make_float4(facc[0], facc[1], facc[2], facc[3]);
    outp[1] = make_float4(facc[4], facc[5], facc[6], facc[7]);
    outp[2] = make_float4(facc[8], facc[9], facc[10], facc[11]);
    outp[3] = make_float4(facc[12], facc[13], facc[14], facc[15]);
}

// ---------------- per-step K3: deterministic reduce + state update -------------
// Block = 256 thr as (32 cols x 8 chunk-groups). Blocks [0,128): layer1 (32 cols
// each). Blocks [128,192): layer2.
__global__ void __launch_bounds__(256) k_update() {
    __shared__ float s[256];
    int b = blockIdx.x;
    int cx = threadIdx.x & 31;     // col within group
    int gy = threadIdx.x >> 5;     // chunk group 0..7
    if (b < 128) {
        int col = b * 32 + cx;
        float s0 = 0.f;
        // CH0 = 512 chunks -> 64 per group
        #pragma unroll 16
        for (int i = 0; i < 64; i++)
            s0 += g_pbu1[(size_t)(gy * 64 + i) * N1 + col];
        s[threadIdx.x] = s0;
        __syncthreads();
        if (gy == 0) {
            float tot = 0.f;
            #pragma unroll
            for (int g = 0; g < 8; g++) tot += s[g * 32 + cx];
            float bu1 = tot * INV_WSCALE;
            float na = g_ract1[col] + INF1 * (bu1 - g_e1[col]);
            g_ract1[col] = na;
            float ro = sigm3(na);
            g_rout1[col] = ro;
            g_rh1[col] = __float2half(ro);
        }
    } else {
        int col = (b - 128) * 32 + cx;
        float s0 = 0.f;
        // CH1 = 256 chunks -> 32 per group
        #pragma unroll 16
        for (int i = 0; i < 32; i++)
            s0 += g_pbu2[(size_t)(gy * 32 + i) * N2 + col];
        s[threadIdx.x] = s0;
        __syncthreads();
        if (gy == 0) {
            float tot = 0.f;
            #pragma unroll
            for (int g = 0; g < 8; g++) tot += s[g * 32 + cx];
            float bu2 = tot * INV_WSCALE;
            float na = g_ract2[col] + INF2 * bu2;
            g_ract2[col] = na;
            float ro = sigm3(na);
            g_rout2[col] = ro;
            g_rh2[col] = __float2half(ro);
        }
    }
}

// ---------------- output assembly ---------------------------------------------
__global__ void k_output(float* __restrict__ out) {
    int i = blockIdx.x * blockDim.x + threadIdx.x;
    if (i < N0) {
        out[i] = g_e0[i];
    } else if (i < N0 + N1) {
        out[i] = g_e1[i - N0];
    } else if (i < N0 + 2 * N1) {
        out[i] = g_rout1[i - N0 - N1];
    } else if (i < N0 + 2 * N1 + N2) {
        out[i] = g_rout2[i - N0 - 2 * N1];
    }
}

extern "C" void kernel_launch(void* const* d_in, const int* in_sizes, int n_in,
                              void* d_out, int out_size) {
    const float* frame = (const float*)d_in[0];
    const float* W0    = (const float*)d_in[1];
    const float* W1    = (const float*)d_in[2];
    float* out = (float*)d_out;

    const size_t totq = ((size_t)N0 * N1 + (size_t)N1 * N2) / 4;
    int cvt_blocks = (int)((totq + 255) / 256);
    k_convert<<<cvt_blocks, 256>>>(W0, W1);
    k_init<<<24, 256>>>();

    for (int t = 0; t < STEPS; t++) {
        k_forward<<<1536, 256>>>(frame);
        k_transpose<<<1280, 128>>>();
        k_update<<<192, 256>>>();
    }
    k_output<<<72, 256>>>(out);
}

// round 16
// speedup vs baseline: 2.3986x; 1.0933x over previous
#include <cuda_runtime.h>
#include <cuda_bf16.h>
#include <cuda_fp16.h>

#define N0 8192
#define N1 4096
#define N2 2048
#define STEPS 100
#define INF1 0.28f
#define INF2 0.20f
#define WSCALE 4096.0f
#define INV_WSCALE (1.0f / 4096.0f)

// transpose partial chunks: 16 rows each
#define CH0 512   // 8192 / 16
#define CH1 256   // 4096 / 16

// ---------------- scratch (device globals; no allocation in kernel_launch) ----
__device__ __align__(16) unsigned char g_W0f8[(size_t)N0 * N1];   // 32 MB, e4m3 = W0 * 4096
__device__ __align__(16) unsigned char g_W1f8[(size_t)N1 * N2];   // 8 MB,  e4m3 = W1 * 4096
__device__ float g_e0[N0];
__device__ float g_e1[N1];
__device__ float g_ract1[N1], g_rout1[N1];
__device__ float g_ract2[N2], g_rout2[N2];
__device__ __align__(16) __half g_rh1[N1];          // f16 copy of r_out1
__device__ __align__(16) __half g_rh2[N2];          // f16 copy of r_out2
__device__ float g_pbu1[(size_t)CH0 * N1];          // 8 MB
__device__ float g_pbu2[(size_t)CH1 * N2];          // 2 MB

__device__ __forceinline__ float sigm3(float x) {
    // sigmoid(x - 3)
    return 1.0f / (1.0f + expf(3.0f - x));
}

// pack 4 floats -> 4 e4m3 bytes (byte0 = v.x ... byte3 = v.w)
__device__ __forceinline__ unsigned pack4_e4m3(float4 v) {
    unsigned short lo, hi;
    asm("cvt.rn.satfinite.e4m3x2.f32 %0, %1, %2;" : "=h"(lo) : "f"(v.y), "f"(v.x));
    asm("cvt.rn.satfinite.e4m3x2.f32 %0, %1, %2;" : "=h"(hi) : "f"(v.w), "f"(v.z));
    return (unsigned)lo | ((unsigned)hi << 16);
}

// decode u32 (4 e4m3) -> two __half2 (a = vals 0,1 ; b = vals 2,3)
__device__ __forceinline__ void u32_to_2h2(unsigned u, __half2& a, __half2& b) {
    unsigned ra, rb;
    asm("{\n\t"
        ".reg .b16 lo, hi;\n\t"
        "mov.b32 {lo, hi}, %2;\n\t"
        "cvt.rn.f16x2.e4m3x2 %0, lo;\n\t"
        "cvt.rn.f16x2.e4m3x2 %1, hi;\n\t"
        "}"
        : "=r"(ra), "=r"(rb) : "r"(u));
    a = *reinterpret_cast<__half2*>(&ra);
    b = *reinterpret_cast<__half2*>(&rb);
}

__device__ __forceinline__ __half2 as_h2(unsigned u) {
    return *reinterpret_cast<__half2*>(&u);
}

// ---------------- one-time per-launch setup ----------------------------------
__global__ void k_convert(const float* __restrict__ W0, const float* __restrict__ W1) {
    size_t i = (size_t)blockIdx.x * blockDim.x + threadIdx.x;
    const size_t n0q = (size_t)N0 * N1 / 4;
    const size_t n1q = (size_t)N1 * N2 / 4;
    if (i < n0q) {
        float4 v = __ldg((const float4*)W0 + i);
        v.x *= WSCALE; v.y *= WSCALE; v.z *= WSCALE; v.w *= WSCALE;
        reinterpret_cast<unsigned*>(g_W0f8)[i] = pack4_e4m3(v);
    } else if (i < n0q + n1q) {
        size_t j = i - n0q;
        float4 v = __ldg((const float4*)W1 + j);
        v.x *= WSCALE; v.y *= WSCALE; v.z *= WSCALE; v.w *= WSCALE;
        reinterpret_cast<unsigned*>(g_W1f8)[j] = pack4_e4m3(v);
    }
}

__global__ void k_init() {
    int j = blockIdx.x * blockDim.x + threadIdx.x;
    float r0 = sigm3(-2.0f);
    if (j < N1) {
        g_ract1[j] = -2.0f;
        g_rout1[j] = r0;
        g_rh1[j] = __float2half(r0);
    } else if (j < N1 + N2) {
        int k = j - N1;
        g_ract2[k] = -2.0f;
        g_rout2[k] = r0;
        g_rh2[k] = __float2half(r0);
    }
}

// dot of one fp8 uint4 (16 w) against 16 r halves (2 uint4 of __half2), f16 chain
__device__ __forceinline__ void dot16_f8(uint4 wq, uint4 rq0, uint4 rq1, float& acc) {
    __half2 h = __float2half2_rn(0.0f);
    __half2 a, b;
    u32_to_2h2(wq.x, a, b);
    h = __hfma2(a, as_h2(rq0.x), h);
    h = __hfma2(b, as_h2(rq0.y), h);
    u32_to_2h2(wq.y, a, b);
    h = __hfma2(a, as_h2(rq0.z), h);
    h = __hfma2(b, as_h2(rq0.w), h);
    u32_to_2h2(wq.z, a, b);
    h = __hfma2(a, as_h2(rq1.x), h);
    h = __hfma2(b, as_h2(rq1.y), h);
    u32_to_2h2(wq.w, a, b);
    h = __hfma2(a, as_h2(rq1.z), h);
    h = __hfma2(b, as_h2(rq1.w), h);
    float2 f = __half22float2(h);
    acc += f.x + f.y;
}

// ---------------- per-step K1: forward matvecs --------------------------------
// e0 = frame - W0 @ r1 ;  e1 = r1 - W1 @ r2
// 1 row per warp. Blocks [0,1024): W0 (8192 warps -> 8192 rows).
// Blocks [1024,1536): W1 (4096 warps -> 4096 rows).
__global__ void __launch_bounds__(256) k_forward(const float* __restrict__ frame) {
    int tid = threadIdx.x, lane = tid & 31, warp = tid >> 5;
    int b = blockIdx.x;
    if (b < 1024) {
        int row = b * 8 + warp;              // 0..8191
        const uint4* w0 = (const uint4*)(g_W0f8 + (size_t)row * N1);
        const uint4* rp = (const uint4*)g_rh1;   // 512 uint4 = 4096 halves
        float a0 = 0.f;
        // 256 uint4 per row (16 fp8 each), 8 iters per lane
        #pragma unroll
        for (int i = 0; i < 8; i++) {
            int c = lane + i * 32;
            uint4 rq0 = __ldg(rp + 2 * c);
            uint4 rq1 = __ldg(rp + 2 * c + 1);
            dot16_f8(__ldg(w0 + c), rq0, rq1, a0);
        }
        #pragma unroll
        for (int o = 16; o; o >>= 1) a0 += __shfl_xor_sync(0xFFFFFFFFu, a0, o);
        if (lane == 0) g_e0[row] = frame[row] - a0 * INV_WSCALE;
    } else {
        int row = (b - 1024) * 8 + warp;     // 0..4095
        const uint4* w0 = (const uint4*)(g_W1f8 + (size_t)row * N2);
        const uint4* rp = (const uint4*)g_rh2;   // 256 uint4 = 2048 halves
        float a0 = 0.f;
        // 128 uint4 per row, 4 iters per lane
        #pragma unroll
        for (int i = 0; i < 4; i++) {
            int c = lane + i * 32;
            uint4 rq0 = __ldg(rp + 2 * c);
            uint4 rq1 = __ldg(rp + 2 * c + 1);
            dot16_f8(__ldg(w0 + c), rq0, rq1, a0);
        }
        #pragma unroll
        for (int o = 16; o; o >>= 1) a0 += __shfl_xor_sync(0xFFFFFFFFu, a0, o);
        if (lane == 0) g_e1[row] = g_rout1[row] - a0 * INV_WSCALE;
    }
}

// ---------------- per-step K2: transpose matvec partials -----------------------
// One block = 16 rows x FULL matrix width -> each inner iteration reads one
// complete row CONTIGUOUSLY across the block; rows sequential -> each block
// sweeps a contiguous 64KB (W0) / 32KB (W1) DRAM span, same walk as k_forward.
// Blocks [0,512): W0 chunks (256 thr x 16 cols each = 4096 cols).
// Blocks [512,768): W1 chunks (256 thr x 8 cols each = 2048 cols).
__global__ void __launch_bounds__(256) k_transpose() {
    __shared__ __half2 s_eh[16];
    int tid = threadIdx.x;
    int b = blockIdx.x;

    if (b < 512) {
        int chunk = b;                       // 0..511
        int row0 = chunk * 16;
        int col0 = tid * 16;                 // 0..4080
        if (tid < 16) s_eh[tid] = __float2half2_rn(g_e0[row0 + tid]);
        __syncthreads();

        const unsigned char* wbase = g_W0f8 + (size_t)row0 * N1 + col0;

        // 4-deep prefetch ring over 16 row loads (uint4 = 16 fp8)
        uint4 p0 = *reinterpret_cast<const uint4*>(wbase + (size_t)0 * N1);
        uint4 p1 = *reinterpret_cast<const uint4*>(wbase + (size_t)1 * N1);
        uint4 p2 = *reinterpret_cast<const uint4*>(wbase + (size_t)2 * N1);
        uint4 p3 = *reinterpret_cast<const uint4*>(wbase + (size_t)3 * N1);

        __half2 acc[8];
        #pragma unroll
        for (int k = 0; k < 8; k++) acc[k] = __float2half2_rn(0.0f);

        #pragma unroll
        for (int r = 0; r < 16; r++) {
            uint4 u;
            if ((r & 3) == 0) u = p0;
            else if ((r & 3) == 1) u = p1;
            else if ((r & 3) == 2) u = p2;
            else u = p3;
            if (r + 4 < 16) {
                uint4 nv = *reinterpret_cast<const uint4*>(wbase + (size_t)(r + 4) * N1);
                if ((r & 3) == 0) p0 = nv;
                else if ((r & 3) == 1) p1 = nv;
                else if ((r & 3) == 2) p2 = nv;
                else p3 = nv;
            }
            __half2 ev = s_eh[r];
            __half2 a, bb;
            u32_to_2h2(u.x, a, bb);
            acc[0] = __hfma2(a, ev, acc[0]);
            acc[1] = __hfma2(bb, ev, acc[1]);
            u32_to_2h2(u.y, a, bb);
            acc[2] = __hfma2(a, ev, acc[2]);
            acc[3] = __hfma2(bb, ev, acc[3]);
            u32_to_2h2(u.z, a, bb);
            acc[4] = __hfma2(a, ev, acc[4]);
            acc[5] = __hfma2(bb, ev, acc[5]);
            u32_to_2h2(u.w, a, bb);
            acc[6] = __hfma2(a, ev, acc[6]);
            acc[7] = __hfma2(bb, ev, acc[7]);
        }

        float facc[16];
        #pragma unroll
        for (int k = 0; k < 8; k++) {
            float2 f = __half22float2(acc[k]);
            facc[2 * k]     = f.x;
            facc[2 * k + 1] = f.y;
        }
        float4* outp = reinterpret_cast<float4*>(&g_pbu1[(size_t)chunk * N1 + col0]);
        outp[0] = make_float4(facc[0], facc[1], facc[2], facc[3]);
        outp[1] = make_float4(facc[4], facc[5], facc[6], facc[7]);
        outp[2] = make_float4(facc[8], facc[9], facc[10], facc[11]);
        outp[3] = make_float4(facc[12], facc[13], facc[14], facc[15]);
    } else {
        int chunk = b - 512;                 // 0..255
        int row0 = chunk * 16;
        int col0 = tid * 8;                  // 0..2040
        if (tid < 16) s_eh[tid] = __float2half2_rn(g_e1[row0 + tid]);
        __syncthreads();

        const unsigned char* wbase = g_W1f8 + (size_t)row0 * N2 + col0;

        // 4-deep prefetch ring over 16 row loads (uint2 = 8 fp8)
        uint2 p0 = *reinterpret_cast<const uint2*>(wbase + (size_t)0 * N2);
        uint2 p1 = *reinterpret_cast<const uint2*>(wbase + (size_t)1 * N2);
        uint2 p2 = *reinterpret_cast<const uint2*>(wbase + (size_t)2 * N2);
        uint2 p3 = *reinterpret_cast<const uint2*>(wbase + (size_t)3 * N2);

        __half2 acc[4];
        #pragma unroll
        for (int k = 0; k < 4; k++) acc[k] = __float2half2_rn(0.0f);

        #pragma unroll
        for (int r = 0; r < 16; r++) {
            uint2 u;
            if ((r & 3) == 0) u = p0;
            else if ((r & 3) == 1) u = p1;
            else if ((r & 3) == 2) u = p2;
            else u = p3;
            if (r + 4 < 16) {
                uint2 nv = *reinterpret_cast<const uint2*>(wbase + (size_t)(r + 4) * N2);
                if ((r & 3) == 0) p0 = nv;
                else if ((r & 3) == 1) p1 = nv;
                else if ((r & 3) == 2) p2 = nv;
                else p3 = nv;
            }
            __half2 ev = s_eh[r];
            __half2 a, bb;
            u32_to_2h2(u.x, a, bb);
            acc[0] = __hfma2(a, ev, acc[0]);
            acc[1] = __hfma2(bb, ev, acc[1]);
            u32_to_2h2(u.y, a, bb);
            acc[2] = __hfma2(a, ev, acc[2]);
            acc[3] = __hfma2(bb, ev, acc[3]);
        }

        float facc[8];
        #pragma unroll
        for (int k = 0; k < 4; k++) {
            float2 f = __half22float2(acc[k]);
            facc[2 * k]     = f.x;
            facc[2 * k + 1] = f.y;
        }
        float4* outp = reinterpret_cast<float4*>(&g_pbu2[(size_t)chunk * N2 + col0]);
        outp[0] = make_float4(facc[0], facc[1], facc[2], facc[3]);
        outp[1] = make_float4(facc[4], facc[5], facc[6], facc[7]);
    }
}

// ---------------- per-step K3: deterministic reduce + state update -------------
// Block = 256 thr as (32 cols x 8 chunk-groups). Blocks [0,128): layer1 (32 cols
// each). Blocks [128,192): layer2.
__global__ void __launch_bounds__(256) k_update() {
    __shared__ float s[256];
    int b = blockIdx.x;
    int cx = threadIdx.x & 31;     // col within group
    int gy = threadIdx.x >> 5;     // chunk group 0..7
    if (b < 128) {
        int col = b * 32 + cx;
        float s0 = 0.f;
        // CH0 = 512 chunks -> 64 per group
        #pragma unroll 16
        for (int i = 0; i < 64; i++)
            s0 += g_pbu1[(size_t)(gy * 64 + i) * N1 + col];
        s[threadIdx.x] = s0;
        __syncthreads();
        if (gy == 0) {
            float tot = 0.f;
            #pragma unroll
            for (int g = 0; g < 8; g++) tot += s[g * 32 + cx];
            float bu1 = tot * INV_WSCALE;
            float na = g_ract1[col] + INF1 * (bu1 - g_e1[col]);
            g_ract1[col] = na;
            float ro = sigm3(na);
            g_rout1[col] = ro;
            g_rh1[col] = __float2half(ro);
        }
    } else {
        int col = (b - 128) * 32 + cx;
        float s0 = 0.f;
        // CH1 = 256 chunks -> 32 per group
        #pragma unroll 16
        for (int i = 0; i < 32; i++)
            s0 += g_pbu2[(size_t)(gy * 32 + i) * N2 + col];
        s[threadIdx.x] = s0;
        __syncthreads();
        if (gy == 0) {
            float tot = 0.f;
            #pragma unroll
            for (int g = 0; g < 8; g++) tot += s[g * 32 + cx];
            float bu2 = tot * INV_WSCALE;
            float na = g_ract2[col] + INF2 * bu2;
            g_ract2[col] = na;
            float ro = sigm3(na);
            g_rout2[col] = ro;
            g_rh2[col] = __float2half(ro);
        }
    }
}

// ---------------- output assembly ---------------------------------------------
__global__ void k_output(float* __restrict__ out) {
    int i = blockIdx.x * blockDim.x + threadIdx.x;
    if (i < N0) {
        out[i] = g_e0[i];
    } else if (i < N0 + N1) {
        out[i] = g_e1[i - N0];
    } else if (i < N0 + 2 * N1) {
        out[i] = g_rout1[i - N0 - N1];
    } else if (i < N0 + 2 * N1 + N2) {
        out[i] = g_rout2[i - N0 - 2 * N1];
    }
}

extern "C" void kernel_launch(void* const* d_in, const int* in_sizes, int n_in,
                              void* d_out, int out_size) {
    const float* frame = (const float*)d_in[0];
    const float* W0    = (const float*)d_in[1];
    const float* W1    = (const float*)d_in[2];
    float* out = (float*)d_out;

    const size_t totq = ((size_t)N0 * N1 + (size_t)N1 * N2) / 4;
    int cvt_blocks = (int)((totq + 255) / 256);
    k_convert<<<cvt_blocks, 256>>>(W0, W1);
    k_init<<<24, 256>>>();

    for (int t = 0; t < STEPS; t++) {
        k_forward<<<1536, 256>>>(frame);
        k_transpose<<<768, 256>>>();
        k_update<<<192, 256>>>();
    }
    k_output<<<72, 256>>>(out);
}